// round 8
// baseline (speedup 1.0000x reference)
#include <cuda_runtime.h>
#include <cuda_fp16.h>
#include <cstdint>

#define BB 1024   // batch
#define DD 512    // latent dim
#define HH 1024   // MLP hidden
#define TT 64     // time points

// ---------------------------------------------------------------------------
// Persistent device state (no allocs allowed).
// ---------------------------------------------------------------------------
__device__ __align__(16) float g_z  [BB * DD];   // current z (fp32)
__device__ __align__(16) float g_acc[BB * DD];   // k1 + 2k2 + 2k3
__device__ __align__(16) __half g_zin[BB * DD];  // stage input (fp16)
__device__ __align__(16) __half g_h  [BB * HH];  // hidden activation (fp16)
__device__ __align__(16) __half g_W1h[DD * HH];
__device__ __align__(16) __half g_W2h[HH * DD];

// reduction tile row stride (fp32), padded => conflict-free
#define RSTR 68

// ---------------------------------------------------------------------------
// PTX helpers
// ---------------------------------------------------------------------------
__device__ __forceinline__ void cpa16(void* dst, const void* src) {
    uint32_t d = (uint32_t)__cvta_generic_to_shared(dst);
    asm volatile("cp.async.cg.shared.global [%0], [%1], 16;\n" :: "r"(d), "l"(src));
}
__device__ __forceinline__ void cp_commit() {
    asm volatile("cp.async.commit_group;\n" ::: "memory");
}
template <int N>
__device__ __forceinline__ void cp_wait() {
    asm volatile("cp.async.wait_group %0;\n" :: "n"(N) : "memory");
}
__device__ __forceinline__ void ldsm4(uint32_t* r, const __half* p) {
    uint32_t a = (uint32_t)__cvta_generic_to_shared(p);
    asm volatile("ldmatrix.sync.aligned.m8n8.x4.shared.b16 {%0,%1,%2,%3},[%4];\n"
                 : "=r"(r[0]), "=r"(r[1]), "=r"(r[2]), "=r"(r[3]) : "r"(a));
}
__device__ __forceinline__ void ldsm4t(uint32_t* r, const __half* p) {
    uint32_t a = (uint32_t)__cvta_generic_to_shared(p);
    asm volatile("ldmatrix.sync.aligned.m8n8.x4.trans.shared.b16 {%0,%1,%2,%3},[%4];\n"
                 : "=r"(r[0]), "=r"(r[1]), "=r"(r[2]), "=r"(r[3]) : "r"(a));
}
__device__ __forceinline__ void mma_f16(float* c, const uint32_t* a, uint32_t b0, uint32_t b1) {
    asm volatile("mma.sync.aligned.m16n8k16.row.col.f32.f16.f16.f32 "
                 "{%0,%1,%2,%3}, {%4,%5,%6,%7}, {%8,%9}, {%0,%1,%2,%3};\n"
                 : "+f"(c[0]), "+f"(c[1]), "+f"(c[2]), "+f"(c[3])
                 : "r"(a[0]), "r"(a[1]), "r"(a[2]), "r"(a[3]), "r"(b0), "r"(b1));
}

// ---------------------------------------------------------------------------
// Mainloop: CTA tile MT(M) x 64(N); KG k-groups x (MT/16) position-warps,
// each position warp owns a 32x32 tile over its 32-wide k-slice.
// Buffer k-extent BK = KG*32.  Threads = KG*(MT/16)*32.
// A: [M,KDIM] row-major fp16.  B: [KDIM,NDIM] row-major fp16.
// On exit: per-k-group partial tiles are in smem red regions
// (kg * MT*RSTR), and all threads are synced.
// ---------------------------------------------------------------------------
template <int KDIM, int NDIM, int KG, int MT>
__device__ __forceinline__ void mainloop(
    const __half* __restrict__ A, const __half* __restrict__ B,
    int m0, int n0, char* smbase)
{
    constexpr int MPOS  = MT / 32;
    constexpr int P     = MPOS * 2;        // position warps per k-group
    constexpr int NTHR  = KG * P * 32;
    constexpr int BK    = KG * 32;
    constexpr int ASTR  = BK + 8;
    constexpr int BSTR  = 72;
    constexpr int ABYTE = MT * ASTR * 2;
    constexpr int BBYTE = BK * BSTR * 2;
    constexpr int BUF   = ABYTE + BBYTE;
    constexpr int NT    = KDIM / BK;       // 8 for both gemms

    const int tid  = threadIdx.x;
    const int wid  = tid >> 5;
    const int lane = tid & 31;
    const int kg   = wid / P;
    const int pos  = wid % P;
    const int wm = (pos % MPOS) * 32;
    const int wn = (pos / MPOS) * 32;
    const int lr  = lane & 15;
    const int lc8 = (lane >> 4) * 8;

    float c[2][4][4] = {};

    auto load_tile = [&](int it, int b) {
        const int kk = it * BK;
        __half* sA = (__half*)(smbase + b * BUF);
        __half* sB = (__half*)(smbase + b * BUF + ABYTE);
#pragma unroll
        for (int ca = tid; ca < MT * (BK / 8); ca += NTHR) {
            int r = ca / (BK / 8), cc = (ca % (BK / 8)) * 8;
            cpa16(sA + r * ASTR + cc, A + (size_t)(m0 + r) * KDIM + kk + cc);
        }
#pragma unroll
        for (int cb = tid; cb < BK * 8; cb += NTHR) {
            int rb = cb >> 3, nb = (cb & 7) * 8;
            cpa16(sB + rb * BSTR + nb, B + (size_t)(kk + rb) * NDIM + n0 + nb);
        }
        cp_commit();
    };

    auto compute = [&](int b) {
        const __half* sA = (const __half*)(smbase + b * BUF);
        const __half* sB = (const __half*)(smbase + b * BUF + ABYTE);
        uint32_t av[2][2][4], bv[2][2][4];
#pragma unroll
        for (int s = 0; s < 2; s++) {                      // hoist all LDSM
            const int kb = kg * 32 + s * 16;
#pragma unroll
            for (int mt = 0; mt < 2; mt++)
                ldsm4(av[s][mt], sA + (wm + mt * 16 + lr) * ASTR + kb + lc8);
#pragma unroll
            for (int g = 0; g < 2; g++)
                ldsm4t(bv[s][g], sB + (kb + lr) * BSTR + wn + g * 16 + lc8);
        }
#pragma unroll
        for (int s = 0; s < 2; s++)
#pragma unroll
            for (int mt = 0; mt < 2; mt++)
#pragma unroll
                for (int nt = 0; nt < 4; nt++) {
                    const int g = nt >> 1, w = (nt & 1) * 2;
                    mma_f16(c[mt][nt], av[s][mt], bv[s][g][w], bv[s][g][w + 1]);
                }
    };

    load_tile(0, 0);
    load_tile(1, 1);
#pragma unroll 1
    for (int it = 0; it < NT; it++) {
        cp_wait<1>();        // tile `it` resident
        __syncthreads();     // all warps done with buffer (it+2)%3
        if (it + 2 < NT) load_tile(it + 2, (it + 2) % 3);
        compute(it % 3);
    }
    __syncthreads();         // tiles dead; smem reusable as reduction buffer

    // Dump this k-group's partials.
    float* red = (float*)smbase + kg * (MT * RSTR);
    const int er = lane >> 2, ec = (lane & 3) * 2;
#pragma unroll
    for (int mt = 0; mt < 2; mt++)
#pragma unroll
        for (int nt = 0; nt < 4; nt++)
#pragma unroll
            for (int h = 0; h < 2; h++) {
                int lm = wm + mt * 16 + er + h * 8;
                int ln = wn + nt * 8 + ec;
                *reinterpret_cast<float2*>(&red[lm * RSTR + ln]) =
                    make_float2(c[mt][nt][2 * h], c[mt][nt][2 * h + 1]);
            }
    __syncthreads();
}

// ---------------------------------------------------------------------------
// GEMM1: h = tanh(zin @ W1 + b1) -> g_h.
// Tile 128x64, KG=2, 512 thr.  grid (16, 8) = 128 CTAs (one wave).
// ---------------------------------------------------------------------------
#define SMEM1 (3 * (128 * 72 * 2 + 64 * 72 * 2))       // 82944
__global__ void __launch_bounds__(512, 1) k_gemm1(const float* __restrict__ b1) {
    extern __shared__ __align__(16) char sm[];
    const int m0 = blockIdx.y * 128, n0 = blockIdx.x * 64;
    mainloop<DD, HH, 2, 128>(g_zin, g_W1h, m0, n0, sm);

    // Final pass: 512 threads x 8 float2 pairs over the 128x64 tile.
    const float* red = (const float*)sm;
    constexpr int RSZ = 128 * RSTR;
    const int tid = threadIdx.x;
#pragma unroll
    for (int j = 0; j < 8; j++) {
        int p  = tid + j * 512;
        int lm = p >> 5, ln = (p & 31) * 2;
        int off = lm * RSTR + ln;
        float2 r0 = *reinterpret_cast<const float2*>(&red[off]);
        float2 r1 = *reinterpret_cast<const float2*>(&red[RSZ + off]);
        int gn = n0 + ln;
        float2 bv = *reinterpret_cast<const float2*>(&b1[gn]);
        float v0 = tanhf(r0.x + r1.x + bv.x);
        float v1 = tanhf(r0.y + r1.y + bv.y);
        *reinterpret_cast<__half2*>(&g_h[(size_t)(m0 + lm) * HH + gn]) =
            __halves2half2(__float2half(v0), __float2half(v1));
    }
}

// ---------------------------------------------------------------------------
// GEMM2 + RK4 combine.  Tile 64x64, KG=4, 512 thr.  grid (8, 16) = 128 CTAs.
// ---------------------------------------------------------------------------
#define SMEM2 (3 * (64 * 136 * 2 + 128 * 72 * 2))      // 107520
__global__ void __launch_bounds__(512, 1) k_gemm2(const float* __restrict__ b2,
                                                  const float* __restrict__ t,
                                                  int step, int stage,
                                                  float* __restrict__ traj) {
    extern __shared__ __align__(16) char sm[];
    const int m0 = blockIdx.y * 64, n0 = blockIdx.x * 64;
    mainloop<HH, DD, 4, 64>(g_h, g_W2h, m0, n0, sm);

    // Final pass: 512 threads x 4 float2 pairs over the 64x64 tile.
    const float* red = (const float*)sm;
    constexpr int RSZ = 64 * RSTR;
    const float dt = t[step + 1] - t[step];
    const int tid = threadIdx.x;
#pragma unroll
    for (int j = 0; j < 4; j++) {
        int p  = tid + j * 512;
        int lm = p >> 5, ln = (p & 31) * 2;
        int off = lm * RSTR + ln;
        float2 r0 = *reinterpret_cast<const float2*>(&red[off]);
        float2 r1 = *reinterpret_cast<const float2*>(&red[RSZ + off]);
        float2 r2 = *reinterpret_cast<const float2*>(&red[2 * RSZ + off]);
        float2 r3 = *reinterpret_cast<const float2*>(&red[3 * RSZ + off]);
        int gn = n0 + ln;
        float2 bv = *reinterpret_cast<const float2*>(&b2[gn]);
        float k0 = r0.x + r1.x + r2.x + r3.x + bv.x;
        float k1 = r0.y + r1.y + r2.y + r3.y + bv.y;
        int idx = (m0 + lm) * DD + gn;
        float2 zv = *reinterpret_cast<const float2*>(&g_z[idx]);
        float zi0, zi1;
        if (stage == 0) {
            *reinterpret_cast<float2*>(&g_acc[idx]) = make_float2(k0, k1);
            zi0 = zv.x + 0.5f * dt * k0;
            zi1 = zv.y + 0.5f * dt * k1;
        } else if (stage == 1) {
            float2 a = *reinterpret_cast<const float2*>(&g_acc[idx]);
            *reinterpret_cast<float2*>(&g_acc[idx]) =
                make_float2(a.x + 2.f * k0, a.y + 2.f * k1);
            zi0 = zv.x + 0.5f * dt * k0;
            zi1 = zv.y + 0.5f * dt * k1;
        } else if (stage == 2) {
            float2 a = *reinterpret_cast<const float2*>(&g_acc[idx]);
            *reinterpret_cast<float2*>(&g_acc[idx]) =
                make_float2(a.x + 2.f * k0, a.y + 2.f * k1);
            zi0 = zv.x + dt * k0;
            zi1 = zv.y + dt * k1;
        } else {
            float2 a = *reinterpret_cast<const float2*>(&g_acc[idx]);
            zi0 = zv.x + (dt * (1.0f / 6.0f)) * (a.x + k0);
            zi1 = zv.y + (dt * (1.0f / 6.0f)) * (a.y + k1);
            *reinterpret_cast<float2*>(&g_z[idx]) = make_float2(zi0, zi1);
            *reinterpret_cast<float2*>(&traj[(size_t)(step + 1) * BB * DD + idx]) =
                make_float2(zi0, zi1);
        }
        *reinterpret_cast<__half2*>(&g_zin[idx]) =
            __halves2half2(__float2half(zi0), __float2half(zi1));
    }
}

// ---------------------------------------------------------------------------
// Setup kernels
// ---------------------------------------------------------------------------
__global__ void convert_kernel(const float* __restrict__ src,
                               __half* __restrict__ dst, int n) {
    int i = blockIdx.x * 256 + threadIdx.x;
    if (i < n) dst[i] = __float2half(src[i]);
}

__global__ void init_kernel(const float* __restrict__ z0, float* __restrict__ traj) {
    int i = blockIdx.x * 256 + threadIdx.x;
    if (i < BB * DD) {
        float v = z0[i];
        g_z[i]   = v;
        traj[i]  = v;
        g_zin[i] = __float2half(v);
    }
}

// ---------------------------------------------------------------------------
extern "C" void kernel_launch(void* const* d_in, const int* in_sizes, int n_in,
                              void* d_out, int out_size) {
    const float* z0 = (const float*)d_in[0];
    const float* t  = (const float*)d_in[1];
    const float* W1 = (const float*)d_in[2];
    const float* b1 = (const float*)d_in[3];
    const float* W2 = (const float*)d_in[4];
    const float* b2 = (const float*)d_in[5];
    float* traj = (float*)d_out;

    __half *w1h, *w2h;
    cudaGetSymbolAddress((void**)&w1h, g_W1h);
    cudaGetSymbolAddress((void**)&w2h, g_W2h);

    cudaFuncSetAttribute(k_gemm1, cudaFuncAttributeMaxDynamicSharedMemorySize, SMEM1);
    cudaFuncSetAttribute(k_gemm2, cudaFuncAttributeMaxDynamicSharedMemorySize, SMEM2);

    convert_kernel<<<(DD * HH + 255) / 256, 256>>>(W1, w1h, DD * HH);
    convert_kernel<<<(HH * DD + 255) / 256, 256>>>(W2, w2h, HH * DD);
    init_kernel<<<(BB * DD + 255) / 256, 256>>>(z0, traj);

    dim3 grid1(HH / 64, BB / 128);  // 16 x 8 = 128 CTAs
    dim3 grid2(DD / 64, BB / 64);   // 8 x 16 = 128 CTAs

    for (int step = 0; step < TT - 1; step++) {
        for (int s = 0; s < 4; s++) {
            k_gemm1<<<grid1, 512, SMEM1>>>(b1);
            k_gemm2<<<grid2, 512, SMEM2>>>(b2, t, step, s, traj);
        }
    }
}

// round 9
// speedup vs baseline: 1.0434x; 1.0434x over previous
#include <cuda_runtime.h>
#include <cuda_fp16.h>
#include <cstdint>

#define BB 1024   // batch
#define DD 512    // latent dim
#define HH 1024   // MLP hidden
#define TT 64     // time points

// ---------------------------------------------------------------------------
// Persistent device state (no allocs allowed).
// ---------------------------------------------------------------------------
__device__ __align__(16) float g_z  [BB * DD];   // current z (fp32)
__device__ __align__(16) float g_acc[BB * DD];   // k1 + 2k2 + 2k3
__device__ __align__(16) __half g_zin[BB * DD];  // stage input (fp16)
__device__ __align__(16) __half g_h  [BB * HH];  // hidden activation (fp16)
__device__ __align__(16) __half g_W1h[DD * HH];
__device__ __align__(16) __half g_W2h[HH * DD];

#define RSTR 68   // reduction row stride (fp32), padded => conflict-free

// ---------------------------------------------------------------------------
// PTX helpers
// ---------------------------------------------------------------------------
__device__ __forceinline__ void cpa16(void* dst, const void* src) {
    uint32_t d = (uint32_t)__cvta_generic_to_shared(dst);
    asm volatile("cp.async.cg.shared.global [%0], [%1], 16;\n" :: "r"(d), "l"(src));
}
__device__ __forceinline__ void cp_commit() {
    asm volatile("cp.async.commit_group;\n" ::: "memory");
}
template <int N>
__device__ __forceinline__ void cp_wait() {
    asm volatile("cp.async.wait_group %0;\n" :: "n"(N) : "memory");
}
__device__ __forceinline__ void ldsm4(uint32_t* r, const __half* p) {
    uint32_t a = (uint32_t)__cvta_generic_to_shared(p);
    asm volatile("ldmatrix.sync.aligned.m8n8.x4.shared.b16 {%0,%1,%2,%3},[%4];\n"
                 : "=r"(r[0]), "=r"(r[1]), "=r"(r[2]), "=r"(r[3]) : "r"(a));
}
__device__ __forceinline__ void ldsm4t(uint32_t* r, const __half* p) {
    uint32_t a = (uint32_t)__cvta_generic_to_shared(p);
    asm volatile("ldmatrix.sync.aligned.m8n8.x4.trans.shared.b16 {%0,%1,%2,%3},[%4];\n"
                 : "=r"(r[0]), "=r"(r[1]), "=r"(r[2]), "=r"(r[3]) : "r"(a));
}
__device__ __forceinline__ void mma_f16(float* c, const uint32_t* a, uint32_t b0, uint32_t b1) {
    asm volatile("mma.sync.aligned.m16n8k16.row.col.f32.f16.f16.f32 "
                 "{%0,%1,%2,%3}, {%4,%5,%6,%7}, {%8,%9}, {%0,%1,%2,%3};\n"
                 : "+f"(c[0]), "+f"(c[1]), "+f"(c[2]), "+f"(c[3])
                 : "r"(a[0]), "r"(a[1]), "r"(a[2]), "r"(a[3]), "r"(b0), "r"(b1));
}
__device__ __forceinline__ float tanh_fast(float x) {
    float y;
    asm("tanh.approx.f32 %0, %1;\n" : "=f"(y) : "f"(x));
    return y;
}

// ===========================================================================
// GEMM1 (full-resident): h = tanh(zin @ W1 + b1) -> g_h.
// Tile 128(M) x 64(N), FULL K=512 resident in smem. One load burst, one
// sync, then barrier-free compute. 512 thr = KG(2) x 8 pos-warps (32x32).
// grid (16, 8) = 128 CTAs (one wave).
// ---------------------------------------------------------------------------
#define A1STR 520                          // 512 + 8 halves
#define SA1_BYTES (128 * A1STR * 2)        // 133120
#define SB1_BYTES (512 * 72 * 2)           // 73728
#define SMEM1 (SA1_BYTES + SB1_BYTES)      // 206848
__global__ void __launch_bounds__(512, 1) k_gemm1(const float* __restrict__ b1) {
    extern __shared__ __align__(16) char sm[];
    __half* sA = (__half*)sm;
    __half* sB = (__half*)(sm + SA1_BYTES);
    const int m0 = blockIdx.y * 128, n0 = blockIdx.x * 64;

    const int tid  = threadIdx.x;
    const int wid  = tid >> 5;
    const int lane = tid & 31;
    const int kg   = wid >> 3;            // 2 k-groups (k-slice 256)
    const int pos  = wid & 7;
    const int wm = (pos & 3) * 32;        // 4 m-positions
    const int wn = (pos >> 2) * 32;       // 2 n-positions
    const int lr  = lane & 15;
    const int lc8 = (lane >> 4) * 8;

    // ---- Single load burst: A 128x512 (8192 chunks), B 512x64 (4096). ----
#pragma unroll
    for (int j = 0; j < 16; j++) {
        int ca = tid + j * 512;
        int r = ca >> 6, cc = (ca & 63) * 8;       // 64 chunks per A row
        cpa16(sA + r * A1STR + cc, g_zin + (size_t)(m0 + r) * DD + cc);
    }
#pragma unroll
    for (int j = 0; j < 8; j++) {
        int cb = tid + j * 512;
        int rb = cb >> 3, nb = (cb & 7) * 8;       // 8 chunks per B row
        cpa16(sB + rb * 72 + nb, g_W1h + (size_t)rb * HH + n0 + nb);
    }
    cp_commit();
    cp_wait<0>();
    __syncthreads();

    // ---- Barrier-free compute: 16 k16 steps over this k-group's slice. ----
    float c[2][4][4] = {};
#pragma unroll
    for (int ks = 0; ks < 16; ks++) {
        const int kb = kg * 256 + ks * 16;
        uint32_t av[2][4], bv[2][4];
#pragma unroll
        for (int mt = 0; mt < 2; mt++)
            ldsm4(av[mt], sA + (wm + mt * 16 + lr) * A1STR + kb + lc8);
#pragma unroll
        for (int g = 0; g < 2; g++)
            ldsm4t(bv[g], sB + (kb + lr) * 72 + wn + g * 16 + lc8);
#pragma unroll
        for (int mt = 0; mt < 2; mt++)
#pragma unroll
            for (int nt = 0; nt < 4; nt++) {
                const int g = nt >> 1, w = (nt & 1) * 2;
                mma_f16(c[mt][nt], av[mt], bv[g][w], bv[g][w + 1]);
            }
    }
    __syncthreads();         // tiles dead; reuse smem for reduction

    // ---- Cross-k-group reduction (2 partials) + epilogue. ----
    float* red = (float*)sm + kg * (128 * RSTR);
    const int er = lane >> 2, ec = (lane & 3) * 2;
#pragma unroll
    for (int mt = 0; mt < 2; mt++)
#pragma unroll
        for (int nt = 0; nt < 4; nt++)
#pragma unroll
            for (int h = 0; h < 2; h++) {
                int lm = wm + mt * 16 + er + h * 8;
                int ln = wn + nt * 8 + ec;
                *reinterpret_cast<float2*>(&red[lm * RSTR + ln]) =
                    make_float2(c[mt][nt][2 * h], c[mt][nt][2 * h + 1]);
            }
    __syncthreads();

    const float* r0p = (const float*)sm;
    constexpr int RSZ = 128 * RSTR;
#pragma unroll
    for (int j = 0; j < 8; j++) {
        int p  = tid + j * 512;
        int lm = p >> 5, ln = (p & 31) * 2;
        int off = lm * RSTR + ln;
        float2 r0 = *reinterpret_cast<const float2*>(&r0p[off]);
        float2 r1 = *reinterpret_cast<const float2*>(&r0p[RSZ + off]);
        int gn = n0 + ln;
        float2 bv = *reinterpret_cast<const float2*>(&b1[gn]);
        float v0 = tanh_fast(r0.x + r1.x + bv.x);
        float v1 = tanh_fast(r0.y + r1.y + bv.y);
        *reinterpret_cast<__half2*>(&g_h[(size_t)(m0 + lm) * HH + gn]) =
            __halves2half2(__float2half(v0), __float2half(v1));
    }
}

// ===========================================================================
// GEMM2 + RK4 combine (streaming, 4-stage): k = h @ W2 + b2.
// Tile 64x64, KG=4 (BK=128), 512 thr, grid (8,16) = 128 CTAs.
// ---------------------------------------------------------------------------
#define A2STR 136                                   // 128 + 8
#define ABYTE2 (64 * A2STR * 2)                     // 17408
#define BBYTE2 (128 * 72 * 2)                       // 18432
#define BUF2   (ABYTE2 + BBYTE2)                    // 35840
#define SMEM2  (4 * BUF2)                           // 143360
__global__ void __launch_bounds__(512, 1) k_gemm2(const float* __restrict__ b2,
                                                  const float* __restrict__ t,
                                                  int step, int stage,
                                                  float* __restrict__ traj) {
    extern __shared__ __align__(16) char sm[];
    const int m0 = blockIdx.y * 64, n0 = blockIdx.x * 64;

    const int tid  = threadIdx.x;
    const int wid  = tid >> 5;
    const int lane = tid & 31;
    const int kg   = wid >> 2;            // 4 k-groups
    const int pos  = wid & 3;
    const int wm = (pos & 1) * 32;
    const int wn = (pos >> 1) * 32;
    const int lr  = lane & 15;
    const int lc8 = (lane >> 4) * 8;

    float c[2][4][4] = {};

    auto load_tile = [&](int it, int b) {
        const int kk = it * 128;
        __half* sA = (__half*)(sm + b * BUF2);
        __half* sB = (__half*)(sm + b * BUF2 + ABYTE2);
#pragma unroll
        for (int j = 0; j < 2; j++) {
            int ca = tid + j * 512;                   // A: 64 x 16 chunks
            int r = ca >> 4, cc = (ca & 15) * 8;
            cpa16(sA + r * A2STR + cc, g_h + (size_t)(m0 + r) * HH + kk + cc);
            int cb = tid + j * 512;                   // B: 128 x 8 chunks
            int rb = cb >> 3, nb = (cb & 7) * 8;
            cpa16(sB + rb * 72 + nb, g_W2h + (size_t)(kk + rb) * DD + n0 + nb);
        }
        cp_commit();
    };

    auto compute = [&](int b) {
        const __half* sA = (const __half*)(sm + b * BUF2);
        const __half* sB = (const __half*)(sm + b * BUF2 + ABYTE2);
        uint32_t av[2][2][4], bv[2][2][4];
#pragma unroll
        for (int s = 0; s < 2; s++) {
            const int kb = kg * 32 + s * 16;
#pragma unroll
            for (int mt = 0; mt < 2; mt++)
                ldsm4(av[s][mt], sA + (wm + mt * 16 + lr) * A2STR + kb + lc8);
#pragma unroll
            for (int g = 0; g < 2; g++)
                ldsm4t(bv[s][g], sB + (kb + lr) * 72 + wn + g * 16 + lc8);
        }
#pragma unroll
        for (int s = 0; s < 2; s++)
#pragma unroll
            for (int mt = 0; mt < 2; mt++)
#pragma unroll
                for (int nt = 0; nt < 4; nt++) {
                    const int g = nt >> 1, w = (nt & 1) * 2;
                    mma_f16(c[mt][nt], av[s][mt], bv[s][g][w], bv[s][g][w + 1]);
                }
    };

    load_tile(0, 0);
    load_tile(1, 1);
    load_tile(2, 2);
#pragma unroll 1
    for (int it = 0; it < 8; it++) {
        if (it < 6)       cp_wait<2>();
        else if (it == 6) cp_wait<1>();
        else              cp_wait<0>();
        __syncthreads();
        if (it + 3 < 8) load_tile(it + 3, (it + 3) & 3);
        compute(it & 3);
    }
    __syncthreads();

    // Reduction dump (4 partials).
    float* red = (float*)sm + kg * (64 * RSTR);
    const int er = lane >> 2, ec = (lane & 3) * 2;
#pragma unroll
    for (int mt = 0; mt < 2; mt++)
#pragma unroll
        for (int nt = 0; nt < 4; nt++)
#pragma unroll
            for (int h = 0; h < 2; h++) {
                int lm = wm + mt * 16 + er + h * 8;
                int ln = wn + nt * 8 + ec;
                *reinterpret_cast<float2*>(&red[lm * RSTR + ln]) =
                    make_float2(c[mt][nt][2 * h], c[mt][nt][2 * h + 1]);
            }
    __syncthreads();

    // Final pass: reduce + bias + RK4 stage update.
    const float* rp = (const float*)sm;
    constexpr int RSZ = 64 * RSTR;
    const float dt = t[step + 1] - t[step];
#pragma unroll
    for (int j = 0; j < 4; j++) {
        int p  = tid + j * 512;
        int lm = p >> 5, ln = (p & 31) * 2;
        int off = lm * RSTR + ln;
        float2 r0 = *reinterpret_cast<const float2*>(&rp[off]);
        float2 r1 = *reinterpret_cast<const float2*>(&rp[RSZ + off]);
        float2 r2 = *reinterpret_cast<const float2*>(&rp[2 * RSZ + off]);
        float2 r3 = *reinterpret_cast<const float2*>(&rp[3 * RSZ + off]);
        int gn = n0 + ln;
        float2 bv = *reinterpret_cast<const float2*>(&b2[gn]);
        float k0 = r0.x + r1.x + r2.x + r3.x + bv.x;
        float k1 = r0.y + r1.y + r2.y + r3.y + bv.y;
        int idx = (m0 + lm) * DD + gn;
        float2 zv = *reinterpret_cast<const float2*>(&g_z[idx]);
        float zi0, zi1;
        if (stage == 0) {
            *reinterpret_cast<float2*>(&g_acc[idx]) = make_float2(k0, k1);
            zi0 = zv.x + 0.5f * dt * k0;
            zi1 = zv.y + 0.5f * dt * k1;
        } else if (stage == 1) {
            float2 a = *reinterpret_cast<const float2*>(&g_acc[idx]);
            *reinterpret_cast<float2*>(&g_acc[idx]) =
                make_float2(a.x + 2.f * k0, a.y + 2.f * k1);
            zi0 = zv.x + 0.5f * dt * k0;
            zi1 = zv.y + 0.5f * dt * k1;
        } else if (stage == 2) {
            float2 a = *reinterpret_cast<const float2*>(&g_acc[idx]);
            *reinterpret_cast<float2*>(&g_acc[idx]) =
                make_float2(a.x + 2.f * k0, a.y + 2.f * k1);
            zi0 = zv.x + dt * k0;
            zi1 = zv.y + dt * k1;
        } else {
            float2 a = *reinterpret_cast<const float2*>(&g_acc[idx]);
            zi0 = zv.x + (dt * (1.0f / 6.0f)) * (a.x + k0);
            zi1 = zv.y + (dt * (1.0f / 6.0f)) * (a.y + k1);
            *reinterpret_cast<float2*>(&g_z[idx]) = make_float2(zi0, zi1);
            *reinterpret_cast<float2*>(&traj[(size_t)(step + 1) * BB * DD + idx]) =
                make_float2(zi0, zi1);
        }
        *reinterpret_cast<__half2*>(&g_zin[idx]) =
            __halves2half2(__float2half(zi0), __float2half(zi1));
    }
}

// ---------------------------------------------------------------------------
// Setup kernels
// ---------------------------------------------------------------------------
__global__ void convert_kernel(const float* __restrict__ src,
                               __half* __restrict__ dst, int n) {
    int i = blockIdx.x * 256 + threadIdx.x;
    if (i < n) dst[i] = __float2half(src[i]);
}

__global__ void init_kernel(const float* __restrict__ z0, float* __restrict__ traj) {
    int i = blockIdx.x * 256 + threadIdx.x;
    if (i < BB * DD) {
        float v = z0[i];
        g_z[i]   = v;
        traj[i]  = v;
        g_zin[i] = __float2half(v);
    }
}

// ---------------------------------------------------------------------------
extern "C" void kernel_launch(void* const* d_in, const int* in_sizes, int n_in,
                              void* d_out, int out_size) {
    const float* z0 = (const float*)d_in[0];
    const float* t  = (const float*)d_in[1];
    const float* W1 = (const float*)d_in[2];
    const float* b1 = (const float*)d_in[3];
    const float* W2 = (const float*)d_in[4];
    const float* b2 = (const float*)d_in[5];
    float* traj = (float*)d_out;

    __half *w1h, *w2h;
    cudaGetSymbolAddress((void**)&w1h, g_W1h);
    cudaGetSymbolAddress((void**)&w2h, g_W2h);

    cudaFuncSetAttribute(k_gemm1, cudaFuncAttributeMaxDynamicSharedMemorySize, SMEM1);
    cudaFuncSetAttribute(k_gemm2, cudaFuncAttributeMaxDynamicSharedMemorySize, SMEM2);

    convert_kernel<<<(DD * HH + 255) / 256, 256>>>(W1, w1h, DD * HH);
    convert_kernel<<<(HH * DD + 255) / 256, 256>>>(W2, w2h, HH * DD);
    init_kernel<<<(BB * DD + 255) / 256, 256>>>(z0, traj);

    dim3 grid1(HH / 64, BB / 128);  // 16 x 8 = 128 CTAs
    dim3 grid2(DD / 64, BB / 64);   // 8 x 16 = 128 CTAs

    for (int step = 0; step < TT - 1; step++) {
        for (int s = 0; s < 4; s++) {
            k_gemm1<<<grid1, 512, SMEM1>>>(b1);
            k_gemm2<<<grid2, 512, SMEM2>>>(b2, t, step, s, traj);
        }
    }
}